// round 5
// baseline (speedup 1.0000x reference)
#include <cuda_runtime.h>
#include <cuda_bf16.h>

#define N_NODES   4000000
#define N_GRAPHS  4096
#define D_FEAT    8
#define N_CLASSES 10
#define SEGS_PER_BLOCK 4            // 8 warps = 4 warp-pairs, 1 segment per pair
#define N_BLOCKS (N_GRAPHS / SEGS_PER_BLOCK)
#define FULL 0xFFFFFFFFu

// batch_ids may be int64 OR int32 (JAX under default x64=False silently makes
// them int32). Values < 4096, so in the int64 case every high word is 0:
// viewing the buffer as int32, element N_NODES-1 is an int64 high word (==0)
// or the max sorted int32 id (>0).
__device__ __forceinline__ int id_at(const int* __restrict__ ids32, bool is64, int i) {
    return is64 ? ids32[2 * i] : ids32[i];
}

// float4 load with 256B L2 prefetch hint (contiguous stream).
__device__ __forceinline__ float4 ldg_pf(const float4* __restrict__ p) {
    float4 v;
    asm("ld.global.L2::256B.v4.f32 {%0,%1,%2,%3}, [%4];"
        : "=f"(v.x), "=f"(v.y), "=f"(v.z), "=f"(v.w) : "l"(p));
    return v;
}

// Half-warp cooperative 16-ary lower_bound of v over sorted ids in [lo, hi).
__device__ __forceinline__ int kary_lower_bound(
    const int* __restrict__ ids32, bool is64, int v,
    int lo, int hi, int sub, int half_shift)
{
    const unsigned hmask = 0xFFFFu << half_shift;
    while (hi - lo > 16) {
        const int range = hi - lo;
        const int pos = lo + (int)(((long long)range * (sub + 1)) >> 4);
        const bool less = id_at(ids32, is64, pos - 1) < v;
        const unsigned ball = __ballot_sync(hmask, less);
        const int cnt = __popc((ball >> half_shift) & 0xFFFFu);
        const int nlo = lo + (int)(((long long)range * cnt) >> 4);
        const int nhi = (cnt == 16) ? hi
                      : lo + (int)(((long long)range * (cnt + 1)) >> 4);
        lo = nlo; hi = nhi;
    }
    const int pos = lo + sub;
    const bool less = (pos < hi) ? (id_at(ids32, is64, pos) < v) : false;
    const unsigned ball = __ballot_sync(hmask, less);
    return lo + __popc((ball >> half_shift) & 0xFFFFu);
}

__global__ __launch_bounds__(256, 6) void fused_pool_gemm_kernel(
    const float4* __restrict__ x4,
    const int*    __restrict__ ids32,
    const float*  __restrict__ W,      // [10, 8]
    const float*  __restrict__ b,      // [10]
    float*        __restrict__ out)    // [4096, 10]
{
    __shared__ float psum[8][D_FEAT];   // per-warp partial pooled sums

    const int warp = threadIdx.x >> 5;
    const int lane = threadIdx.x & 31;
    const int pair = warp >> 1;                  // 0..3
    const int half = warp & 1;                   // which half of the pair
    const int g    = blockIdx.x * SEGS_PER_BLOCK + pair;   // segment id

    // ---- Phase 1: per-warp cooperative boundary search ----
    const bool is64 = (ids32[N_NODES - 1] == 0);
    const int half_shift = lane & 16;
    const int sub = lane & 15;
    const int v = (half_shift == 0) ? g : g + 1;

    int res;
    if (v >= N_GRAPHS) {
        res = N_NODES;
    } else {
        const long long approx = ((long long)v * N_NODES) >> 12;  // v * N/B
        int lo = (int)(approx - 32768); if (lo < 0) lo = 0;
        int hi = (int)(approx + 32768); if (hi > N_NODES) hi = N_NODES;
        const bool ok_lo = (lo == 0)       || (id_at(ids32, is64, lo - 1) < v);
        const bool ok_hi = (hi == N_NODES) || (id_at(ids32, is64, hi) >= v);
        if (!(ok_lo && ok_hi)) { lo = 0; hi = N_NODES; }
        res = kary_lower_bound(ids32, is64, v, lo, hi, sub, half_shift);
    }
    __syncwarp(FULL);
    const int start = __shfl_sync(FULL, res, 0);
    const int end   = __shfl_sync(FULL, res, 16);
    const int cnt   = end - start;
    const long long base = (long long)start * 2;   // float4 units
    const int n4 = cnt * 2;

    // ---- Phase 2: two warps stream one segment (64-lane logical stride) ----
    const int gl = half * 32 + lane;   // 0..63
    float4 a0 = make_float4(0.f,0.f,0.f,0.f);
    float4 a1 = make_float4(0.f,0.f,0.f,0.f);

    int j = gl;
    while (j + 192 < n4) {      // 4 loads x 64 logical lanes per chunk
        float4 v0 = ldg_pf(&x4[base + j      ]);
        float4 v1 = ldg_pf(&x4[base + j +  64]);
        float4 v2 = ldg_pf(&x4[base + j + 128]);
        float4 v3 = ldg_pf(&x4[base + j + 192]);
        a0.x += v0.x; a0.y += v0.y; a0.z += v0.z; a0.w += v0.w;
        a1.x += v1.x; a1.y += v1.y; a1.z += v1.z; a1.w += v1.w;
        a0.x += v2.x; a0.y += v2.y; a0.z += v2.z; a0.w += v2.w;
        a1.x += v3.x; a1.y += v3.y; a1.z += v3.z; a1.w += v3.w;
        j += 256;
    }
    for (; j < n4; j += 64) {
        float4 vv = ldg_pf(&x4[base + j]);
        a0.x += vv.x; a0.y += vv.y; a0.z += vv.z; a0.w += vv.w;
    }
    a0.x += a1.x; a0.y += a1.y; a0.z += a1.z; a0.w += a1.w;

    // Parity-preserving butterfly: lane 0 -> cols 0-3, lane 1 -> cols 4-7.
    #pragma unroll
    for (int m = 16; m >= 2; m >>= 1) {
        a0.x += __shfl_xor_sync(FULL, a0.x, m);
        a0.y += __shfl_xor_sync(FULL, a0.y, m);
        a0.z += __shfl_xor_sync(FULL, a0.z, m);
        a0.w += __shfl_xor_sync(FULL, a0.w, m);
    }
    if (lane == 0) {
        psum[warp][0] = a0.x; psum[warp][1] = a0.y;
        psum[warp][2] = a0.z; psum[warp][3] = a0.w;
    } else if (lane == 1) {
        psum[warp][4] = a0.x; psum[warp][5] = a0.y;
        psum[warp][6] = a0.z; psum[warp][7] = a0.w;
    }
    __syncthreads();

    // ---- Phase 3: even warp of each pair combines halves + tiny GEMM ----
    if (half == 0 && lane < N_CLASSES) {
        const float inv = (cnt > 0) ? (1.0f / (float)cnt) : 0.0f;
        const float* w = W + lane * D_FEAT;
        float r = __ldg(&b[lane]);
        #pragma unroll
        for (int k = 0; k < D_FEAT; k++)
            r += (psum[warp][k] + psum[warp + 1][k]) * inv * __ldg(&w[k]);
        out[g * N_CLASSES + lane] = r;
    }
}

extern "C" void kernel_launch(void* const* d_in, const int* in_sizes, int n_in,
                              void* d_out, int out_size) {
    // Bind inputs by element count (robust to metadata ordering):
    //   x: 32,000,000 f32 | batch_ids: 4,000,000 | W: 80 | b: 10
    const float* x   = nullptr;
    const void*  ids = nullptr;
    const float* W   = nullptr;
    const float* b   = nullptr;
    for (int i = 0; i < n_in; i++) {
        switch (in_sizes[i]) {
            case N_NODES * D_FEAT:   x   = (const float*)d_in[i]; break;
            case N_NODES:            ids = d_in[i];               break;
            case N_CLASSES * D_FEAT: W   = (const float*)d_in[i]; break;
            case N_CLASSES:          b   = (const float*)d_in[i]; break;
            default: break; // input_ids / attention_mask: unused
        }
    }
    float* out = (float*)d_out;

    fused_pool_gemm_kernel<<<N_BLOCKS, 256>>>(
        (const float4*)x, (const int*)ids, W, b, out);
}